// round 13
// baseline (speedup 1.0000x reference)
#include <cuda_runtime.h>
#include <cuda_fp16.h>
#include <cstdint>
#include <cstddef>

// Problem sizes
static constexpr int M = 8192;   // tokens
static constexpr int K = 4096;   // in features
static constexpr int N = 4096;   // out features

// GEMM tiling: CTA 128x256x64, 8 warps (2 M x 4 N), warp tile 64x64, 256 threads.
static constexpr int BM = 128;
static constexpr int BN = 256;
static constexpr int BK = 64;                    // 64 fp16 = 128 B per row
static constexpr int NIT = K / BK;               // 64
static constexpr int STAGES = 4;
static constexpr int A_STAGE_BYTES = BM * 128;   // 16 KB
static constexpr int B_STAGE_BYTES = BN * 128;   // 32 KB
static constexpr int STAGE_BYTES = A_STAGE_BYTES + B_STAGE_BYTES;  // 48 KB
static constexpr int DYN_SMEM = 1024 + STAGES * STAGE_BYTES;       // ~193 KB

// Scratch (static device arrays are allowed; cudaMalloc is not)
__device__ __half g_A[(size_t)M * K];   // sign(x) as fp16, [M,K] row-major
__device__ __half g_B[(size_t)N * K];   // W^T as fp16,     [N,K] row-major

// ---------------- PTX helpers (baseline sm_103, no 'a' features) ----------------
__device__ __forceinline__ uint32_t smem_u32(const void* p) {
    uint32_t a;
    asm("{ .reg .u64 t; cvta.to.shared.u64 t, %1; cvt.u32.u64 %0, t; }" : "=r"(a) : "l"(p));
    return a;
}
__device__ __forceinline__ void cp_async16(uint32_t s, const void* g) {
    asm volatile("cp.async.cg.shared.global [%0], [%1], 16;" :: "r"(s), "l"(g));
}
__device__ __forceinline__ void cp_commit() {
    asm volatile("cp.async.commit_group;" ::: "memory");
}
template <int NWAIT>
__device__ __forceinline__ void cp_wait() {
    asm volatile("cp.async.wait_group %0;" :: "n"(NWAIT) : "memory");
}
__device__ __forceinline__ void ldsm_x4(uint32_t& r0, uint32_t& r1, uint32_t& r2, uint32_t& r3,
                                        uint32_t addr) {
    asm volatile("ldmatrix.sync.aligned.m8n8.x4.shared.b16 {%0,%1,%2,%3}, [%4];"
                 : "=r"(r0), "=r"(r1), "=r"(r2), "=r"(r3) : "r"(addr));
}
__device__ __forceinline__ void mma16816(float& d0, float& d1, float& d2, float& d3,
                                         uint32_t a0, uint32_t a1, uint32_t a2, uint32_t a3,
                                         uint32_t b0, uint32_t b1) {
    asm volatile(
        "mma.sync.aligned.m16n8k16.row.col.f32.f16.f16.f32 "
        "{%0,%1,%2,%3}, {%4,%5,%6,%7}, {%8,%9}, {%0,%1,%2,%3};"
        : "+f"(d0), "+f"(d1), "+f"(d2), "+f"(d3)
        : "r"(a0), "r"(a1), "r"(a2), "r"(a3), "r"(b0), "r"(b1));
}
// SW128-style swizzle: XOR 16B-chunk index with (row & 7)
__device__ __forceinline__ uint32_t swz(uint32_t off) { return off ^ ((off >> 3) & 0x70); }

// ---------------- Kernel 1: fused prep ----------------
static constexpr int BIN_BLOCKS = 4096;
static constexpr int WCONV_BLOCKS = (N / 32) * (K / 64);   // 8192
__global__ void prep_kernel(const float4* __restrict__ x4, const float* __restrict__ W) {
    if (blockIdx.x < BIN_BLOCKS) {
        const int n4 = (M * K) / 4;
        int i = blockIdx.x * 256 + threadIdx.x;
        const int stride = BIN_BLOCKS * 256;
        const __half one = __float2half_rn(1.0f);
        const __half neg = __float2half_rn(-1.0f);
        uint2* a8 = reinterpret_cast<uint2*>(g_A);
        for (; i < n4; i += stride) {
            float4 v = x4[i];
            __half2 h0 = __halves2half2(v.x > 0.0f ? one : neg, v.y > 0.0f ? one : neg);
            __half2 h1 = __halves2half2(v.z > 0.0f ? one : neg, v.w > 0.0f ? one : neg);
            uint2 pk;
            pk.x = *reinterpret_cast<uint32_t*>(&h0);
            pk.y = *reinterpret_cast<uint32_t*>(&h1);
            a8[i] = pk;
        }
    } else {
        __shared__ float t[64][33];
        const int bid = blockIdx.x - BIN_BLOCKS;
        const int n0 = (bid & 127) * 32;       // N/32 = 128
        const int k0 = (bid >> 7) * 64;
        const int tx = threadIdx.x & 31, ty = threadIdx.x >> 5;   // 32 x 8
#pragma unroll
        for (int r = 0; r < 8; ++r)
            t[ty + 8 * r][tx] = W[(size_t)(k0 + ty + 8 * r) * N + n0 + tx];
        __syncthreads();
#pragma unroll
        for (int r = 0; r < 4; ++r) {
            const int n = ty + 8 * r;          // 0..31
            const __half2 h = __floats2half2_rn(t[2 * tx][n], t[2 * tx + 1][n]);
            *reinterpret_cast<__half2*>(g_B + (size_t)(n0 + n) * K + k0 + 2 * tx) = h;
        }
    }
}

// ---------------- Kernel 2: mma.sync fp16 GEMM + bias ----------------
// Quarter of a stage load: 3 LDGSTS per thread (chunks [q*768, (q+1)*768)).
__device__ __forceinline__ void load_stage_q(uint32_t tile0, int m0, int n0, int k_it, int slot,
                                             int tid, int q) {
    const int k0 = k_it * BK;
    const uint32_t sa = tile0 + slot * STAGE_BYTES;
    const uint32_t sbm = sa + A_STAGE_BYTES;
#pragma unroll
    for (int c = q * 768 + tid; c < (q + 1) * 768; c += 256) {
        if (c < 1024) {
            const int r = c >> 3, j = c & 7;
            cp_async16(sa + swz((uint32_t)(r * 128 + j * 16)),
                       g_A + (((size_t)(m0 + r)) << 12) + k0 + (j << 3));
        } else {
            const int c2 = c - 1024;
            const int r = c2 >> 3, j = c2 & 7;
            cp_async16(sbm + swz((uint32_t)(r * 128 + j * 16)),
                       g_B + (((size_t)(n0 + r)) << 12) + k0 + (j << 3));
        }
    }
}
__device__ __forceinline__ void load_stage(uint32_t tile0, int m0, int n0, int k_it, int slot,
                                           int tid) {
#pragma unroll
    for (int q = 0; q < 4; ++q) load_stage_q(tile0, m0, n0, k_it, slot, tid, q);
}

// Load one kk-step's fragments for this warp: A 4x ldsm.x4, B 4x ldsm.x4.
__device__ __forceinline__ void load_frags(uint32_t af[4][4], uint32_t bf[8][2],
                                           uint32_t sa, uint32_t sbm,
                                           const uint32_t aoff[4], const uint32_t boff[4],
                                           uint32_t kx) {
#pragma unroll
    for (int mi = 0; mi < 4; ++mi)
        ldsm_x4(af[mi][0], af[mi][1], af[mi][2], af[mi][3], sa + (aoff[mi] ^ kx));
#pragma unroll
    for (int pj = 0; pj < 4; ++pj) {
        uint32_t r0, r1, r2, r3;
        ldsm_x4(r0, r1, r2, r3, sbm + (boff[pj] ^ kx));
        bf[pj * 2 + 0][0] = r0; bf[pj * 2 + 0][1] = r1;
        bf[pj * 2 + 1][0] = r2; bf[pj * 2 + 1][1] = r3;
    }
}

__global__ void __launch_bounds__(256, 1) gemm_kernel(float* __restrict__ out,
                                                      const float* __restrict__ bias) {
    extern __shared__ char smem[];
    const uint32_t tile0 = (smem_u32(smem) + 1023) & ~1023u;
    const int tid = threadIdx.x;
    const int wid = tid >> 5;
    const int lane = tid & 31;
    const int m0 = blockIdx.y * BM;
    const int n0 = blockIdx.x * BN;
    const int warp_m = wid & 1;        // 0..1 -> 64 rows each
    const int warp_n = wid >> 1;       // 0..3 -> 64 cols each

    // Swizzled ldmatrix offsets (kk=0).
    uint32_t aoff[4];
#pragma unroll
    for (int mi = 0; mi < 4; ++mi) {
        const int row = warp_m * 64 + mi * 16 + (lane & 15);
        aoff[mi] = swz((uint32_t)(row * 128) + (uint32_t)((lane >> 4) << 4));
    }
    uint32_t boff[4];
#pragma unroll
    for (int pj = 0; pj < 4; ++pj) {
        const int row = warp_n * 64 + pj * 16 + (lane & 7) + ((lane >> 4) << 3);
        boff[pj] = swz((uint32_t)(row * 128) + (uint32_t)(((lane >> 3) & 1) << 4));
    }

    float acc[4][8][4];   // [mi][nj][c]  (128 regs)
#pragma unroll
    for (int mi = 0; mi < 4; ++mi)
#pragma unroll
        for (int nj = 0; nj < 8; ++nj)
#pragma unroll
            for (int c = 0; c < 4; ++c) acc[mi][nj][c] = 0.0f;

    // Prologue: fill stages 0..2
#pragma unroll
    for (int p = 0; p < STAGES - 1; ++p) {
        load_stage(tile0, m0, n0, p, p, tid);
        cp_commit();
    }
    cp_wait<1>();       // stages 0,1 resident
    __syncthreads();

    // Full kk-step double buffer: A 2x16 regs, B 2x16 regs.
    uint32_t af[2][4][4];
    uint32_t bf[2][8][2];
    load_frags(af[0], bf[0], tile0, tile0 + A_STAGE_BYTES, aoff, boff, 0);

    for (int it = 0; it < NIT; ++it) {
        const uint32_t sa = tile0 + (it % STAGES) * STAGE_BYTES;
        const uint32_t sbm = sa + A_STAGE_BYTES;
        const uint32_t sa_n = tile0 + ((it + 1) % STAGES) * STAGE_BYTES;
        const uint32_t sbm_n = sa_n + A_STAGE_BYTES;
        const bool has_next = (it + 1 < NIT);
        const int ld_it = it + STAGES - 1;
        const bool do_load = ld_it < NIT;
        const int ld_slot = ld_it % STAGES;

#pragma unroll
        for (int kk = 0; kk < 4; ++kk) {
            const int cur = kk & 1, nxt = cur ^ 1;
            // Prefetch kk+1 (same stage) or next iter's kk0 (stage it+1, resident).
            if (kk < 3)
                load_frags(af[nxt], bf[nxt], sa, sbm, aoff, boff, (uint32_t)((kk + 1) << 5));
            else if (has_next)
                load_frags(af[nxt], bf[nxt], sa_n, sbm_n, aoff, boff, 0);
            // 32 MMAs of latency cover for the prefetch above.
#pragma unroll
            for (int mi = 0; mi < 4; ++mi)
#pragma unroll
                for (int nj = 0; nj < 8; ++nj)
                    mma16816(acc[mi][nj][0], acc[mi][nj][1], acc[mi][nj][2], acc[mi][nj][3],
                             af[cur][mi][0], af[cur][mi][1], af[cur][mi][2], af[cur][mi][3],
                             bf[cur][nj][0], bf[cur][nj][1]);
            // Staggered global loads: quarter kk of stage it+3, issued behind the MMA drain.
            if (do_load)
                load_stage_q(tile0, m0, n0, ld_it, ld_slot, tid, kk);
        }
        cp_commit();

        // End-of-iter: guarantee stage it+2 resident (next iter's kk3 prefetch);
        // barrier frees stage it's slot for next iter's writers.
        cp_wait<1>();
        __syncthreads();
    }

    // Epilogue
    const int g = lane >> 2, tg = lane & 3;
    float bcol0[8], bcol1[8];
#pragma unroll
    for (int nj = 0; nj < 8; ++nj) {
        const int col = n0 + warp_n * 64 + nj * 8 + tg * 2;
        bcol0[nj] = __ldg(bias + col);
        bcol1[nj] = __ldg(bias + col + 1);
    }
#pragma unroll
    for (int mi = 0; mi < 4; ++mi) {
        const int r0 = m0 + warp_m * 64 + mi * 16 + g;
        float* o0 = out + (size_t)r0 * N;
        float* o1 = out + (size_t)(r0 + 8) * N;
#pragma unroll
        for (int nj = 0; nj < 8; ++nj) {
            const int col = n0 + warp_n * 64 + nj * 8 + tg * 2;
            float2 v0 = make_float2(acc[mi][nj][0] + bcol0[nj], acc[mi][nj][1] + bcol1[nj]);
            float2 v1 = make_float2(acc[mi][nj][2] + bcol0[nj], acc[mi][nj][3] + bcol1[nj]);
            *reinterpret_cast<float2*>(o0 + col) = v0;
            *reinterpret_cast<float2*>(o1 + col) = v1;
        }
    }
}

// ---------------- launch ----------------
extern "C" void kernel_launch(void* const* d_in, const int* in_sizes, int n_in,
                              void* d_out, int out_size) {
    const float* x    = (const float*)d_in[0];
    const float* W    = (const float*)d_in[1];
    const float* bias = (const float*)d_in[2];
    float* out = (float*)d_out;

    prep_kernel<<<BIN_BLOCKS + WCONV_BLOCKS, 256>>>((const float4*)x, W);

    cudaFuncSetAttribute(gemm_kernel, cudaFuncAttributeMaxDynamicSharedMemorySize, DYN_SMEM);
    gemm_kernel<<<dim3(N / BN, M / BM), 256, DYN_SMEM>>>(out, bias);
}